// round 16
// baseline (speedup 1.0000x reference)
#include <cuda_runtime.h>
#include <cuda_bf16.h>
#include <math.h>
#include <stdint.h>

// Problem constants
#define NROWS 32768   // B*H*W
#define CDIM  128
#define KCODES 8192
#define BB 32
#define HH 32
#define WW 32

#define RM 256        // rows per GEMM block
#define KN 256        // codes per outer tile (2 sub-tiles of 128)
#define NTT (KCODES/KN)   // 32 outer tiles
#define MARGIN 3.0f
#define CAP 128

// Output buffer layout: [loss(1)] [out(B*C*H*W)] [perplexity(1)] [idx(NROWS)]
#define OUT_OFF  1
#define PERP_OFF (1 + NROWS*CDIM)
#define IDX_OFF  (PERP_OFF + 1)

// Scratch (static __device__ — no allocations allowed)
__device__ __align__(256) float g_z[NROWS*CDIM];        // projected inputs [N,C] fp32
__device__ __align__(256) __nv_bfloat16 g_zbf[NROWS*CDIM];
__device__ __align__(256) __nv_bfloat16 g_ebf[KCODES*CDIM];
__device__ __align__(256) float g_zsq[NROWS];
__device__ __align__(256) float g_esq[KCODES];
__device__ __align__(256) int   g_ccnt[NROWS];          // candidate counts
__device__ __align__(256) int   g_cidx[NROWS*CAP];      // candidate indices
__device__ float g_wt[CDIM*CDIM];      // W transposed
__device__ int   g_idx[NROWS];
__device__ float g_part[1024];
__device__ unsigned int g_hist[KCODES];

// ---------------------------------------------------------------------------
// helpers
__device__ __forceinline__ void cpa16(uint32_t dst, const void* src) {
    asm volatile("cp.async.ca.shared.global [%0], [%1], 16;" :: "r"(dst), "l"(src));
}
__device__ __forceinline__ void cpa_commit() {
    asm volatile("cp.async.commit_group;" ::: "memory");
}
template <int N>
__device__ __forceinline__ void cpa_wait() {
    asm volatile("cp.async.wait_group %0;" :: "n"(N) : "memory");
}
__device__ __forceinline__ void ldsm4(uint32_t* r, uint32_t addr) {
    asm volatile("ldmatrix.sync.aligned.m8n8.x4.shared.b16 {%0,%1,%2,%3},[%4];"
                 : "=r"(r[0]), "=r"(r[1]), "=r"(r[2]), "=r"(r[3]) : "r"(addr));
}
__device__ __forceinline__ void mma16816(float* d, const uint32_t* a, const uint32_t* b) {
    asm("mma.sync.aligned.m16n8k16.row.col.f32.bf16.bf16.f32 "
        "{%0,%1,%2,%3},{%4,%5,%6,%7},{%8,%9},{%0,%1,%2,%3};"
        : "+f"(d[0]), "+f"(d[1]), "+f"(d[2]), "+f"(d[3])
        : "r"(a[0]), "r"(a[1]), "r"(a[2]), "r"(a[3]), "r"(b[0]), "r"(b[1]));
}
// monotone float<->u32 key for atomicMin on floats (incl. negatives)
__device__ __forceinline__ unsigned fkey(float f) {
    int i = __float_as_int(f);
    return (i >= 0) ? ((unsigned)i | 0x80000000u) : (unsigned)(~i);
}
__device__ __forceinline__ float finv(unsigned u) {
    int i = (u & 0x80000000u) ? (int)(u & 0x7fffffffu) : ~(int)u;
    return __int_as_float(i);
}

// ---------------------------------------------------------------------------
// emb row norms + bf16 conversion + W transpose + hist zero + ccnt zero.
__global__ void k_esq(const float* __restrict__ emb, const float* __restrict__ Wl) {
    int gtid = blockIdx.x * blockDim.x + threadIdx.x;
    if (gtid < CDIM*CDIM) {
        int j = gtid / CDIM, c = gtid % CDIM;
        g_wt[c*CDIM + j] = Wl[gtid];
    }
    if (gtid < KCODES) g_hist[gtid] = 0u;
    if (gtid < NROWS) g_ccnt[gtid] = 0;

    int warp = gtid >> 5;
    int lane = threadIdx.x & 31;
    if (warp >= KCODES) return;
    float4 v = ((const float4*)(emb + (size_t)warp * CDIM))[lane];
    float s = v.x*v.x + v.y*v.y + v.z*v.z + v.w*v.w;
    #pragma unroll
    for (int o = 16; o > 0; o >>= 1) s += __shfl_xor_sync(0xffffffffu, s, o);
    if (lane == 0) g_esq[warp] = s;
    __nv_bfloat162 p0 = __floats2bfloat162_rn(v.x, v.y);
    __nv_bfloat162 p1 = __floats2bfloat162_rn(v.z, v.w);
    uint2 u; u.x = *(unsigned*)&p0; u.y = *(unsigned*)&p1;
    ((uint2*)g_ebf)[warp*32 + lane] = u;
}

// ---------------------------------------------------------------------------
// Linear projection -> g_z (fp32), g_zbf (bf16), fused z row norms -> g_zsq.
__global__ void k_linear(const float* __restrict__ x, const float* __restrict__ bl) {
    __shared__ float xs[32*132 + 64];   // main: xs[c*32+w] (4096); reused padded for zsq
    int bh = blockIdx.x;
    int b = bh >> 5, h = bh & 31;
    int tid = threadIdx.x;          // 128
    int w = tid & 31, cg = tid >> 5;
    const float* xp = x + ((size_t)(b*CDIM) * HH + h) * WW;
    #pragma unroll
    for (int cc = 0; cc < 32; cc++) {
        int c = cg*32 + cc;
        xs[c*WW + w] = xp[(size_t)c * (HH*WW) + w];
    }
    __syncthreads();

    int j = tid;
    float bj = bl[j];
    float acc[WW];
    #pragma unroll
    for (int ww = 0; ww < WW; ww++) acc[ww] = bj;

    #pragma unroll 4
    for (int c = 0; c < CDIM; c++) {
        float wv = g_wt[c*CDIM + j];
        #pragma unroll
        for (int w4 = 0; w4 < WW/4; w4++) {
            float4 xv = *(const float4*)&xs[c*WW + w4*4];
            acc[w4*4+0] += xv.x * wv;
            acc[w4*4+1] += xv.y * wv;
            acc[w4*4+2] += xv.z * wv;
            acc[w4*4+3] += xv.w * wv;
        }
    }
    int nbase = bh * WW;
    #pragma unroll
    for (int ww = 0; ww < WW; ww++) {
        g_z[(size_t)(nbase+ww)*CDIM + j] = acc[ww];
        g_zbf[(size_t)(nbase+ww)*CDIM + j] = __float2bfloat16_rn(acc[ww]);
    }

    // fused zsq: sq_sm[ww*132 + j] = acc[ww]^2; then 4 threads/row reduce.
    __syncthreads();   // xs main use done
    #pragma unroll
    for (int ww = 0; ww < WW; ww++)
        xs[ww*132 + j] = acc[ww] * acc[ww];
    __syncthreads();
    {
        int row = tid >> 2, part = tid & 3;   // 32 rows x 4 parts
        float s = 0.f;
        #pragma unroll
        for (int i = 0; i < 32; i++)
            s += xs[row*132 + part*32 + i];
        s += __shfl_xor_sync(0xffffffffu, s, 1);
        s += __shfl_xor_sync(0xffffffffu, s, 2);
        if (part == 0) g_zsq[nbase + row] = s;
    }
}

// ---------------------------------------------------------------------------
// Single-pass bf16 mma.sync GEMM + running-min threshold + collection.
#define SMEM_GEMM (65536 + 131072 + 2048 + 1024)

__global__ void __launch_bounds__(1024, 1) k_gemm() {
    extern __shared__ char smc[];
    char* zt = smc;                               // 64KB (256 rows)
    char* et = smc + 65536;                       // 2 x 64KB (256 codes each)
    float* ssq = (float*)(smc + 196608);          // 2 x 256
    unsigned* samin = (unsigned*)(smc + 198656);  // 256 running row-min (fkey)

    int tid = threadIdx.x, lane = tid & 31, wid = tid >> 5;
    int warp_m = wid & 7, warp_n = wid >> 3;
    int rowbase = blockIdx.x * RM;

    uint32_t zt_a = (uint32_t)__cvta_generic_to_shared(zt);
    uint32_t et_a = (uint32_t)__cvta_generic_to_shared(et);
    uint32_t ssq_a = (uint32_t)__cvta_generic_to_shared(ssq);

    auto stage_e = [&](int t) {
        int buf = t & 1;
        const char* src = (const char*)g_ebf + (size_t)t * KN * 256;
        uint32_t db = et_a + (uint32_t)buf * 65536u;
        #pragma unroll
        for (int u = 0; u < 4; u++) {
            int i = u*1024 + tid;
            int r = i >> 4, c = i & 15;
            cpa16(db + (uint32_t)(r*16 + (c ^ (r & 7)))*16u, src + r*256 + c*16);
        }
        if (tid < 64)
            cpa16(ssq_a + (uint32_t)buf*1024u + (uint32_t)tid*16u, g_esq + t*KN + tid*4);
    };

    // prologue: z tile (256 rows) + e tile 0
    {
        const char* src = (const char*)g_zbf + (size_t)rowbase * 256;
        #pragma unroll
        for (int u = 0; u < 4; u++) {
            int i = u*1024 + tid;
            int r = i >> 4, c = i & 15;
            cpa16(zt_a + (uint32_t)(r*16 + (c ^ (r & 7)))*16u, src + r*256 + c*16);
        }
        stage_e(0);
        cpa_commit();
    }
    if (tid < 256) samin[tid] = 0xFFFFFFFFu;

    // per-lane row slots: slot = mt*2 + half -> row offset in block
    int rows4[4]; float zsq4[4];
    #pragma unroll
    for (int sl = 0; sl < 4; sl++) {
        int mt = sl >> 1, half = sl & 1;
        rows4[sl] = warp_m*32 + mt*16 + (lane >> 2) + half*8;
        zsq4[sl] = g_zsq[rowbase + rows4[sl]];
    }

    // ldmatrix lane addressing constants
    int hiA = (lane >> 4) & 1;
    int hiB = (lane >> 3) & 1;
    int am7[2]; uint32_t abase[2];
    #pragma unroll
    for (int mt = 0; mt < 2; mt++) {
        int ar = warp_m*32 + mt*16 + (lane & 15);
        am7[mt] = ar & 7; abase[mt] = zt_a + (uint32_t)ar*256u;
    }
    int bm7[2]; uint32_t bbase[2];
    #pragma unroll
    for (int g = 0; g < 2; g++) {
        int br = warp_n*32 + g*16 + (lane & 7) + ((lane >> 4) << 3);
        bm7[g] = br & 7; bbase[g] = et_a + (uint32_t)br*256u;
    }

    for (int t = 0; t < NTT; t++) {
        cpa_wait<0>();     // tile t staged (issued in prev iter / prologue)
        __syncthreads();   // staged visible to all; prev-iter readers done
        if (t + 1 < NTT) { stage_e(t + 1); cpa_commit(); }

        #pragma unroll
        for (int sub = 0; sub < 2; sub++) {
            uint32_t ebb = (uint32_t)(t & 1) * 65536u + (uint32_t)sub * 32768u;

            float acc[2][4][4];
            #pragma unroll
            for (int a = 0; a < 2; a++)
                #pragma unroll
                for (int b = 0; b < 4; b++)
                    #pragma unroll
                    for (int c = 0; c < 4; c++) acc[a][b][c] = 0.f;

            #pragma unroll
            for (int s = 0; s < 8; s++) {
                uint32_t Ar[2][4], Br[2][4];
                #pragma unroll
                for (int mt = 0; mt < 2; mt++) {
                    uint32_t ad = abase[mt] + (uint32_t)(((2*s + hiA) ^ am7[mt]) << 4);
                    ldsm4(Ar[mt], ad);
                }
                #pragma unroll
                for (int g = 0; g < 2; g++) {
                    uint32_t bd = bbase[g] + ebb + (uint32_t)(((2*s + hiB) ^ bm7[g]) << 4);
                    ldsm4(Br[g], bd);
                }
                #pragma unroll
                for (int mt = 0; mt < 2; mt++)
                    #pragma unroll
                    for (int g = 0; g < 2; g++) {
                        mma16816(acc[mt][2*g+0], Ar[mt], &Br[g][0]);
                        mma16816(acc[mt][2*g+1], Ar[mt], &Br[g][2]);
                    }
            }

            // epilogue part 1: d~ = (zsq+esq) - 2*dot, per-slot tile min
            const float* sq = ssq + (t & 1) * 256 + sub * 128;
            float tmin[4];
            #pragma unroll
            for (int sl = 0; sl < 4; sl++) tmin[sl] = 3.0e38f;
            #pragma unroll
            for (int nt = 0; nt < 4; nt++) {
                int cbase = warp_n*32 + nt*8 + (lane & 3)*2;
                float2 es2 = *(const float2*)&sq[cbase];
                #pragma unroll
                for (int mt = 0; mt < 2; mt++) {
                    float d0 = fmaf(-2.f, acc[mt][nt][0], zsq4[mt*2+0] + es2.x);
                    float d1 = fmaf(-2.f, acc[mt][nt][1], zsq4[mt*2+0] + es2.y);
                    float d2 = fmaf(-2.f, acc[mt][nt][2], zsq4[mt*2+1] + es2.x);
                    float d3 = fmaf(-2.f, acc[mt][nt][3], zsq4[mt*2+1] + es2.y);
                    acc[mt][nt][0] = d0; acc[mt][nt][1] = d1;
                    acc[mt][nt][2] = d2; acc[mt][nt][3] = d3;
                    tmin[mt*2+0] = fminf(tmin[mt*2+0], fminf(d0, d1));
                    tmin[mt*2+1] = fminf(tmin[mt*2+1], fminf(d2, d3));
                }
            }
            // merge tile min into running row min. Publish only if improving:
            // skipped atomics are exactly those that cannot lower samin, so
            // the samin value sequence (and thresholds) are unchanged.
            #pragma unroll
            for (int sl = 0; sl < 4; sl++) {
                float v = tmin[sl];
                v = fminf(v, __shfl_xor_sync(0xffffffffu, v, 1));
                v = fminf(v, __shfl_xor_sync(0xffffffffu, v, 2));
                if ((lane & 3) == 0) {
                    unsigned k = fkey(v);
                    if (k < samin[rows4[sl]]) atomicMin(&samin[rows4[sl]], k);
                }
            }
            if (t == 0 && sub == 0) __syncthreads();  // first threshold publish

            // epilogue part 2: collect under running threshold (superset-safe)
            float thr4[4];
            unsigned anyc = 0;
            #pragma unroll
            for (int sl = 0; sl < 4; sl++) {
                thr4[sl] = finv(samin[rows4[sl]]) + MARGIN;
                anyc |= (tmin[sl] <= thr4[sl]) ? 1u : 0u;
            }
            if (__any_sync(0xffffffffu, anyc)) {
                int kt = t * KN + sub * 128;
                #pragma unroll
                for (int nt = 0; nt < 4; nt++) {
                    int cbase = warp_n*32 + nt*8 + (lane & 3)*2;
                    #pragma unroll
                    for (int mt = 0; mt < 2; mt++) {
                        int r0 = rowbase + rows4[mt*2+0];
                        int r1 = rowbase + rows4[mt*2+1];
                        if (acc[mt][nt][0] <= thr4[mt*2+0]) {
                            int p = atomicAdd(&g_ccnt[r0], 1);
                            if (p < CAP) g_cidx[r0*CAP + p] = kt + cbase;
                        }
                        if (acc[mt][nt][1] <= thr4[mt*2+0]) {
                            int p = atomicAdd(&g_ccnt[r0], 1);
                            if (p < CAP) g_cidx[r0*CAP + p] = kt + cbase + 1;
                        }
                        if (acc[mt][nt][2] <= thr4[mt*2+1]) {
                            int p = atomicAdd(&g_ccnt[r1], 1);
                            if (p < CAP) g_cidx[r1*CAP + p] = kt + cbase;
                        }
                        if (acc[mt][nt][3] <= thr4[mt*2+1]) {
                            int p = atomicAdd(&g_ccnt[r1], 1);
                            if (p < CAP) g_cidx[r1*CAP + p] = kt + cbase + 1;
                        }
                    }
                }
            }
        }
        // no extra sync: next-iter top sync orders buffer reuse
    }
}

// ---------------------------------------------------------------------------
// Exact fp32 rescore + idx output + histogram. Warp per row, coalesced lane
// loads, 4 candidates per iteration (ILP). cnt==1 fast path: a 1-element
// collected superset must be the argmin.
__global__ void k_rescore(const float* __restrict__ emb, float* __restrict__ dout) {
    int wid = threadIdx.x >> 5, lane = threadIdx.x & 31;
    int row = blockIdx.x * 8 + wid;
    int cnt = g_ccnt[row];

    float best = 3.0e38f; int bidx = 0x7fffffff;
    if (cnt == 1) {
        bidx = g_cidx[row*CAP];
    } else if (cnt <= CAP) {
        float4 z4 = ((const float4*)(g_z + (size_t)row * CDIM))[lane];
        float zs = g_zsq[row];
        const int4* cp4 = (const int4*)(g_cidx + (size_t)row*CAP);
        for (int c0 = 0; c0 < cnt; c0 += 4) {
            int nc = cnt - c0; if (nc > 4) nc = 4;
            int4 iv = cp4[c0 >> 2];        // row storage is 16B-aligned
            int idx[4] = {iv.x, (nc > 1 ? iv.y : iv.x),
                          (nc > 2 ? iv.z : iv.x), (nc > 3 ? iv.w : iv.x)};
            float p[4];
            #pragma unroll
            for (int j = 0; j < 4; j++) {
                float4 e4 = ((const float4*)(emb + (size_t)idx[j] * CDIM))[lane];
                p[j] = fmaf(z4.x, e4.x, fmaf(z4.y, e4.y, fmaf(z4.z, e4.z, z4.w*e4.w)));
            }
            #pragma unroll
            for (int o = 16; o > 0; o >>= 1) {
                #pragma unroll
                for (int j = 0; j < 4; j++)
                    p[j] += __shfl_xor_sync(0xffffffffu, p[j], o);
            }
            #pragma unroll
            for (int j = 0; j < 4; j++) {
                if (j < nc) {
                    float d = __fsub_rn(__fadd_rn(zs, g_esq[idx[j]]), __fmul_rn(2.0f, p[j]));
                    if (d < best || (d == best && idx[j] < bidx)) { best = d; bidx = idx[j]; }
                }
            }
        }
    } else {
        // overflow fallback: full scan, 4 codes per iteration
        float4 z4 = ((const float4*)(g_z + (size_t)row * CDIM))[lane];
        float zs = g_zsq[row];
        for (int c0 = 0; c0 < KCODES; c0 += 4) {
            float p[4];
            #pragma unroll
            for (int j = 0; j < 4; j++) {
                float4 e4 = ((const float4*)(emb + (size_t)(c0 + j) * CDIM))[lane];
                p[j] = fmaf(z4.x, e4.x, fmaf(z4.y, e4.y, fmaf(z4.z, e4.z, z4.w*e4.w)));
            }
            #pragma unroll
            for (int o = 16; o > 0; o >>= 1) {
                #pragma unroll
                for (int j = 0; j < 4; j++)
                    p[j] += __shfl_xor_sync(0xffffffffu, p[j], o);
            }
            #pragma unroll
            for (int j = 0; j < 4; j++) {
                float d = __fsub_rn(__fadd_rn(zs, g_esq[c0 + j]), __fmul_rn(2.0f, p[j]));
                if (d < best) { best = d; bidx = c0 + j; }
            }
        }
    }
    if (lane == 0) {
        g_idx[row] = bidx;
        dout[IDX_OFF + row] = (float)bidx;
        atomicAdd(&g_hist[bidx], 1u);
    }
}

// ---------------------------------------------------------------------------
// Gather + BCHW output + SSE partials.
__global__ void k_output(const float* __restrict__ emb, float* __restrict__ dout) {
    __shared__ float se[CDIM*(WW+1)];
    __shared__ float sz[CDIM*(WW+1)];
    __shared__ int   sidx[WW];
    __shared__ float sred[8];
    int bh = blockIdx.x;
    int b = bh >> 5, h = bh & 31;
    int nbase = bh * WW;
    int tid = threadIdx.x;   // 256

    if (tid < WW) sidx[tid] = g_idx[nbase + tid];
    __syncthreads();

    for (int e = tid; e < WW*CDIM; e += 256) {
        int w = e >> 7, c = e & 127;
        se[c*(WW+1) + w] = emb[(size_t)sidx[w]*CDIM + c];
        sz[c*(WW+1) + w] = g_z[(size_t)(nbase+w)*CDIM + c];
    }
    __syncthreads();

    float lsse = 0.f;
    for (int e = tid; e < CDIM*WW; e += 256) {
        int c = e >> 5, w = e & 31;
        float q  = se[c*(WW+1) + w];
        float zz = sz[c*(WW+1) + w];
        float df = q - zz;
        lsse += df*df;
        dout[OUT_OFF + (((size_t)(b*CDIM + c))*HH + h)*WW + w] = q;
    }
    #pragma unroll
    for (int o = 16; o > 0; o >>= 1) lsse += __shfl_xor_sync(0xffffffffu, lsse, o);
    if ((tid & 31) == 0) sred[tid >> 5] = lsse;
    __syncthreads();
    if (tid == 0) {
        float s = 0.f;
        #pragma unroll
        for (int i = 0; i < 8; i++) s += sred[i];
        g_part[bh] = s;
    }
}

// ---------------------------------------------------------------------------
// Final scalars, all fp32
__global__ void k_final(float* __restrict__ dout) {
    __shared__ float sr[256];
    int tid = threadIdx.x;
    float s = 0.f;
    for (int i = tid; i < 1024; i += 256) s += g_part[i];
    sr[tid] = s; __syncthreads();
    for (int o = 128; o > 0; o >>= 1) {
        if (tid < o) sr[tid] += sr[tid + o];
        __syncthreads();
    }
    if (tid == 0) {
        float mse = sr[0] / (float)(NROWS*CDIM);
        dout[0] = 1.25f * mse;
    }
    __syncthreads();
    float hs = 0.f;
    for (int k = tid; k < KCODES; k += 256) {
        float p = (float)g_hist[k] / (float)NROWS;
        hs += p * logf(p + 1e-10f);
    }
    sr[tid] = hs; __syncthreads();
    for (int o = 128; o > 0; o >>= 1) {
        if (tid < o) sr[tid] += sr[tid + o];
        __syncthreads();
    }
    if (tid == 0) dout[PERP_OFF] = expf(-sr[0]);
}

// ---------------------------------------------------------------------------
extern "C" void kernel_launch(void* const* d_in, const int* in_sizes, int n_in,
                              void* d_out, int out_size) {
    const float* x   = (const float*)d_in[0];
    const float* Wl  = (const float*)d_in[1];
    const float* bl  = (const float*)d_in[2];
    const float* emb = (const float*)d_in[3];
    float* dout = (float*)d_out;

    cudaFuncSetAttribute(k_gemm, cudaFuncAttributeMaxDynamicSharedMemorySize, SMEM_GEMM);

    k_esq<<<(KCODES*32)/256, 256>>>(emb, Wl);
    k_linear<<<BB*HH, 128>>>(x, bl);
    k_gemm<<<NROWS/RM, 1024, SMEM_GEMM>>>();
    k_rescore<<<NROWS/8, 256>>>(emb, dout);
    k_output<<<BB*HH, 256>>>(emb, dout);
    k_final<<<1, 256>>>(dout);
}

// round 17
// speedup vs baseline: 1.0238x; 1.0238x over previous
#include <cuda_runtime.h>
#include <cuda_bf16.h>
#include <math.h>
#include <stdint.h>

// Problem constants
#define NROWS 32768   // B*H*W
#define CDIM  128
#define KCODES 8192
#define BB 32
#define HH 32
#define WW 32

#define RM 256        // rows per GEMM block
#define KN 256        // codes per outer tile (2 sub-tiles of 128)
#define NTT (KCODES/KN)   // 32 outer tiles
#define MARGIN 3.0f
#define CAP 128

// Output buffer layout: [loss(1)] [out(B*C*H*W)] [perplexity(1)] [idx(NROWS)]
#define OUT_OFF  1
#define PERP_OFF (1 + NROWS*CDIM)
#define IDX_OFF  (PERP_OFF + 1)

// Scratch (static __device__ — no allocations allowed)
__device__ __align__(256) float g_z[NROWS*CDIM];        // projected inputs [N,C] fp32
__device__ __align__(256) __nv_bfloat16 g_zbf[NROWS*CDIM];
__device__ __align__(256) __nv_bfloat16 g_ebf[KCODES*CDIM];
__device__ __align__(256) float g_zsq[NROWS];
__device__ __align__(256) float g_esq[KCODES];
__device__ __align__(256) int   g_ccnt[NROWS];          // candidate counts
__device__ __align__(256) int   g_cidx[NROWS*CAP];      // candidate indices
__device__ float g_wt[CDIM*CDIM];      // W transposed
__device__ int   g_idx[NROWS];
__device__ float g_part[1024];
__device__ unsigned int g_hist[KCODES];
__device__ unsigned int g_done;        // k_output completion counter

// ---------------------------------------------------------------------------
// helpers
__device__ __forceinline__ void cpa16(uint32_t dst, const void* src) {
    asm volatile("cp.async.ca.shared.global [%0], [%1], 16;" :: "r"(dst), "l"(src));
}
__device__ __forceinline__ void cpa_commit() {
    asm volatile("cp.async.commit_group;" ::: "memory");
}
template <int N>
__device__ __forceinline__ void cpa_wait() {
    asm volatile("cp.async.wait_group %0;" :: "n"(N) : "memory");
}
__device__ __forceinline__ void ldsm4(uint32_t* r, uint32_t addr) {
    asm volatile("ldmatrix.sync.aligned.m8n8.x4.shared.b16 {%0,%1,%2,%3},[%4];"
                 : "=r"(r[0]), "=r"(r[1]), "=r"(r[2]), "=r"(r[3]) : "r"(addr));
}
__device__ __forceinline__ void mma16816(float* d, const uint32_t* a, const uint32_t* b) {
    asm("mma.sync.aligned.m16n8k16.row.col.f32.bf16.bf16.f32 "
        "{%0,%1,%2,%3},{%4,%5,%6,%7},{%8,%9},{%0,%1,%2,%3};"
        : "+f"(d[0]), "+f"(d[1]), "+f"(d[2]), "+f"(d[3])
        : "r"(a[0]), "r"(a[1]), "r"(a[2]), "r"(a[3]), "r"(b[0]), "r"(b[1]));
}
// monotone float<->u32 key for atomicMin on floats (incl. negatives)
__device__ __forceinline__ unsigned fkey(float f) {
    int i = __float_as_int(f);
    return (i >= 0) ? ((unsigned)i | 0x80000000u) : (unsigned)(~i);
}
__device__ __forceinline__ float finv(unsigned u) {
    int i = (u & 0x80000000u) ? (int)(u & 0x7fffffffu) : ~(int)u;
    return __int_as_float(i);
}
__device__ __forceinline__ unsigned long long packf2(float lo, float hi) {
    unsigned long long r;
    asm("mov.b64 %0, {%1, %2};" : "=l"(r) : "f"(lo), "f"(hi));
    return r;
}
__device__ __forceinline__ void unpackf2(float& lo, float& hi, unsigned long long v) {
    asm("mov.b64 {%0, %1}, %2;" : "=f"(lo), "=f"(hi) : "l"(v));
}

// ---------------------------------------------------------------------------
// emb row norms + bf16 conversion + W transpose + hist/ccnt/done zero.
__global__ void k_esq(const float* __restrict__ emb, const float* __restrict__ Wl) {
    int gtid = blockIdx.x * blockDim.x + threadIdx.x;
    if (gtid < CDIM*CDIM) {
        int j = gtid / CDIM, c = gtid % CDIM;
        g_wt[c*CDIM + j] = Wl[gtid];
    }
    if (gtid < KCODES) g_hist[gtid] = 0u;
    if (gtid < NROWS) g_ccnt[gtid] = 0;
    if (gtid == 0) g_done = 0u;

    int warp = gtid >> 5;
    int lane = threadIdx.x & 31;
    if (warp >= KCODES) return;
    float4 v = ((const float4*)(emb + (size_t)warp * CDIM))[lane];
    float s = v.x*v.x + v.y*v.y + v.z*v.z + v.w*v.w;
    #pragma unroll
    for (int o = 16; o > 0; o >>= 1) s += __shfl_xor_sync(0xffffffffu, s, o);
    if (lane == 0) g_esq[warp] = s;
    __nv_bfloat162 p0 = __floats2bfloat162_rn(v.x, v.y);
    __nv_bfloat162 p1 = __floats2bfloat162_rn(v.z, v.w);
    uint2 u; u.x = *(unsigned*)&p0; u.y = *(unsigned*)&p1;
    ((uint2*)g_ebf)[warp*32 + lane] = u;
}

// ---------------------------------------------------------------------------
// Linear projection -> g_z (fp32), g_zbf (bf16), fused z row norms -> g_zsq.
// Packed f32x2 FMA: per-lane fma chain identical to the scalar version
// (same c-order) -> z bit-identical (verified round 11: rel_err unchanged).
__global__ void k_linear(const float* __restrict__ x, const float* __restrict__ bl) {
    __shared__ float xs[32*132 + 64];   // main: xs[c*32+w] (4096); reused padded for zsq
    int bh = blockIdx.x;
    int b = bh >> 5, h = bh & 31;
    int tid = threadIdx.x;          // 128
    int w = tid & 31, cg = tid >> 5;
    const float* xp = x + ((size_t)(b*CDIM) * HH + h) * WW;
    #pragma unroll
    for (int cc = 0; cc < 32; cc++) {
        int c = cg*32 + cc;
        xs[c*WW + w] = xp[(size_t)c * (HH*WW) + w];
    }
    __syncthreads();

    int j = tid;
    float bj = bl[j];
    unsigned long long acc2[16];          // rows (2p, 2p+1)
    unsigned long long bj2 = packf2(bj, bj);
    #pragma unroll
    for (int p = 0; p < 16; p++) acc2[p] = bj2;

    #pragma unroll 4
    for (int c = 0; c < CDIM; c++) {
        float wv = g_wt[c*CDIM + j];
        unsigned long long wv2 = packf2(wv, wv);
        #pragma unroll
        for (int w4 = 0; w4 < 8; w4++) {
            float4 xv = *(const float4*)&xs[c*WW + w4*4];
            unsigned long long lo = packf2(xv.x, xv.y);
            unsigned long long hi = packf2(xv.z, xv.w);
            asm("fma.rn.f32x2 %0, %1, %2, %0;" : "+l"(acc2[w4*2+0]) : "l"(lo), "l"(wv2));
            asm("fma.rn.f32x2 %0, %1, %2, %0;" : "+l"(acc2[w4*2+1]) : "l"(hi), "l"(wv2));
        }
    }
    int nbase = bh * WW;
    float accs[WW];
    #pragma unroll
    for (int p = 0; p < 16; p++) {
        float lo, hi;
        unpackf2(lo, hi, acc2[p]);
        accs[2*p+0] = lo; accs[2*p+1] = hi;
        g_z[(size_t)(nbase + 2*p + 0)*CDIM + j] = lo;
        g_z[(size_t)(nbase + 2*p + 1)*CDIM + j] = hi;
        g_zbf[(size_t)(nbase + 2*p + 0)*CDIM + j] = __float2bfloat16_rn(lo);
        g_zbf[(size_t)(nbase + 2*p + 1)*CDIM + j] = __float2bfloat16_rn(hi);
    }

    // fused zsq: sq_sm[ww*132 + j] = accs[ww]^2; then 4 threads/row reduce.
    __syncthreads();   // xs main use done
    #pragma unroll
    for (int ww = 0; ww < WW; ww++)
        xs[ww*132 + j] = accs[ww] * accs[ww];
    __syncthreads();
    {
        int row = tid >> 2, part = tid & 3;   // 32 rows x 4 parts
        float s = 0.f;
        #pragma unroll
        for (int i = 0; i < 32; i++)
            s += xs[row*132 + part*32 + i];
        s += __shfl_xor_sync(0xffffffffu, s, 1);
        s += __shfl_xor_sync(0xffffffffu, s, 2);
        if (part == 0) g_zsq[nbase + row] = s;
    }
}

// ---------------------------------------------------------------------------
// Single-pass bf16 mma.sync GEMM + running-min threshold + collection.
// (exact round-15 / best configuration)
#define SMEM_GEMM (65536 + 131072 + 2048 + 1024)

__global__ void __launch_bounds__(1024, 1) k_gemm() {
    extern __shared__ char smc[];
    char* zt = smc;                               // 64KB (256 rows)
    char* et = smc + 65536;                       // 2 x 64KB (256 codes each)
    float* ssq = (float*)(smc + 196608);          // 2 x 256
    unsigned* samin = (unsigned*)(smc + 198656);  // 256 running row-min (fkey)

    int tid = threadIdx.x, lane = tid & 31, wid = tid >> 5;
    int warp_m = wid & 7, warp_n = wid >> 3;
    int rowbase = blockIdx.x * RM;

    uint32_t zt_a = (uint32_t)__cvta_generic_to_shared(zt);
    uint32_t et_a = (uint32_t)__cvta_generic_to_shared(et);
    uint32_t ssq_a = (uint32_t)__cvta_generic_to_shared(ssq);

    auto stage_e = [&](int t) {
        int buf = t & 1;
        const char* src = (const char*)g_ebf + (size_t)t * KN * 256;
        uint32_t db = et_a + (uint32_t)buf * 65536u;
        #pragma unroll
        for (int u = 0; u < 4; u++) {
            int i = u*1024 + tid;
            int r = i >> 4, c = i & 15;
            cpa16(db + (uint32_t)(r*16 + (c ^ (r & 7)))*16u, src + r*256 + c*16);
        }
        if (tid < 64)
            cpa16(ssq_a + (uint32_t)buf*1024u + (uint32_t)tid*16u, g_esq + t*KN + tid*4);
    };

    // prologue: z tile (256 rows) + e tile 0
    {
        const char* src = (const char*)g_zbf + (size_t)rowbase * 256;
        #pragma unroll
        for (int u = 0; u < 4; u++) {
            int i = u*1024 + tid;
            int r = i >> 4, c = i & 15;
            cpa16(zt_a + (uint32_t)(r*16 + (c ^ (r & 7)))*16u, src + r*256 + c*16);
        }
        stage_e(0);
        cpa_commit();
    }
    if (tid < 256) samin[tid] = 0xFFFFFFFFu;

    // per-lane row slots: slot = mt*2 + half -> row offset in block
    int rows4[4]; float zsq4[4];
    #pragma unroll
    for (int sl = 0; sl < 4; sl++) {
        int mt = sl >> 1, half = sl & 1;
        rows4[sl] = warp_m*32 + mt*16 + (lane >> 2) + half*8;
        zsq4[sl] = g_zsq[rowbase + rows4[sl]];
    }

    // ldmatrix lane addressing constants
    int hiA = (lane >> 4) & 1;
    int hiB = (lane >> 3) & 1;
    int am7[2]; uint32_t abase[2];
    #pragma unroll
    for (int mt = 0; mt < 2; mt++) {
        int ar = warp_m*32 + mt*16 + (lane & 15);
        am7[mt] = ar & 7; abase[mt] = zt_a + (uint32_t)ar*256u;
    }
    int bm7[2]; uint32_t bbase[2];
    #pragma unroll
    for (int g = 0; g < 2; g++) {
        int br = warp_n*32 + g*16 + (lane & 7) + ((lane >> 4) << 3);
        bm7[g] = br & 7; bbase[g] = et_a + (uint32_t)br*256u;
    }

    for (int t = 0; t < NTT; t++) {
        cpa_wait<0>();     // tile t staged (issued in prev iter / prologue)
        __syncthreads();   // staged visible to all; prev-iter readers done
        if (t + 1 < NTT) { stage_e(t + 1); cpa_commit(); }

        #pragma unroll
        for (int sub = 0; sub < 2; sub++) {
            uint32_t ebb = (uint32_t)(t & 1) * 65536u + (uint32_t)sub * 32768u;

            float acc[2][4][4];
            #pragma unroll
            for (int a = 0; a < 2; a++)
                #pragma unroll
                for (int b = 0; b < 4; b++)
                    #pragma unroll
                    for (int c = 0; c < 4; c++) acc[a][b][c] = 0.f;

            #pragma unroll
            for (int s = 0; s < 8; s++) {
                uint32_t Ar[2][4], Br[2][4];
                #pragma unroll
                for (int mt = 0; mt < 2; mt++) {
                    uint32_t ad = abase[mt] + (uint32_t)(((2*s + hiA) ^ am7[mt]) << 4);
                    ldsm4(Ar[mt], ad);
                }
                #pragma unroll
                for (int g = 0; g < 2; g++) {
                    uint32_t bd = bbase[g] + ebb + (uint32_t)(((2*s + hiB) ^ bm7[g]) << 4);
                    ldsm4(Br[g], bd);
                }
                #pragma unroll
                for (int mt = 0; mt < 2; mt++)
                    #pragma unroll
                    for (int g = 0; g < 2; g++) {
                        mma16816(acc[mt][2*g+0], Ar[mt], &Br[g][0]);
                        mma16816(acc[mt][2*g+1], Ar[mt], &Br[g][2]);
                    }
            }

            // epilogue part 1: d~ = (zsq+esq) - 2*dot, per-slot tile min
            const float* sq = ssq + (t & 1) * 256 + sub * 128;
            float tmin[4];
            #pragma unroll
            for (int sl = 0; sl < 4; sl++) tmin[sl] = 3.0e38f;
            #pragma unroll
            for (int nt = 0; nt < 4; nt++) {
                int cbase = warp_n*32 + nt*8 + (lane & 3)*2;
                float2 es2 = *(const float2*)&sq[cbase];
                #pragma unroll
                for (int mt = 0; mt < 2; mt++) {
                    float d0 = fmaf(-2.f, acc[mt][nt][0], zsq4[mt*2+0] + es2.x);
                    float d1 = fmaf(-2.f, acc[mt][nt][1], zsq4[mt*2+0] + es2.y);
                    float d2 = fmaf(-2.f, acc[mt][nt][2], zsq4[mt*2+1] + es2.x);
                    float d3 = fmaf(-2.f, acc[mt][nt][3], zsq4[mt*2+1] + es2.y);
                    acc[mt][nt][0] = d0; acc[mt][nt][1] = d1;
                    acc[mt][nt][2] = d2; acc[mt][nt][3] = d3;
                    tmin[mt*2+0] = fminf(tmin[mt*2+0], fminf(d0, d1));
                    tmin[mt*2+1] = fminf(tmin[mt*2+1], fminf(d2, d3));
                }
            }
            // merge tile min into running row min
            #pragma unroll
            for (int sl = 0; sl < 4; sl++) {
                float v = tmin[sl];
                v = fminf(v, __shfl_xor_sync(0xffffffffu, v, 1));
                v = fminf(v, __shfl_xor_sync(0xffffffffu, v, 2));
                if ((lane & 3) == 0) atomicMin(&samin[rows4[sl]], fkey(v));
            }
            if (t == 0 && sub == 0) __syncthreads();  // first threshold publish

            // epilogue part 2: collect under running threshold (superset-safe)
            float thr4[4];
            unsigned anyc = 0;
            #pragma unroll
            for (int sl = 0; sl < 4; sl++) {
                thr4[sl] = finv(samin[rows4[sl]]) + MARGIN;
                anyc |= (tmin[sl] <= thr4[sl]) ? 1u : 0u;
            }
            if (__any_sync(0xffffffffu, anyc)) {
                int kt = t * KN + sub * 128;
                #pragma unroll
                for (int nt = 0; nt < 4; nt++) {
                    int cbase = warp_n*32 + nt*8 + (lane & 3)*2;
                    #pragma unroll
                    for (int mt = 0; mt < 2; mt++) {
                        int r0 = rowbase + rows4[mt*2+0];
                        int r1 = rowbase + rows4[mt*2+1];
                        if (acc[mt][nt][0] <= thr4[mt*2+0]) {
                            int p = atomicAdd(&g_ccnt[r0], 1);
                            if (p < CAP) g_cidx[r0*CAP + p] = kt + cbase;
                        }
                        if (acc[mt][nt][1] <= thr4[mt*2+0]) {
                            int p = atomicAdd(&g_ccnt[r0], 1);
                            if (p < CAP) g_cidx[r0*CAP + p] = kt + cbase + 1;
                        }
                        if (acc[mt][nt][2] <= thr4[mt*2+1]) {
                            int p = atomicAdd(&g_ccnt[r1], 1);
                            if (p < CAP) g_cidx[r1*CAP + p] = kt + cbase;
                        }
                        if (acc[mt][nt][3] <= thr4[mt*2+1]) {
                            int p = atomicAdd(&g_ccnt[r1], 1);
                            if (p < CAP) g_cidx[r1*CAP + p] = kt + cbase + 1;
                        }
                    }
                }
            }
        }
        // no extra sync: next-iter top sync orders buffer reuse
    }
}

// ---------------------------------------------------------------------------
// Exact fp32 rescore + idx output + histogram. Warp per row, coalesced lane
// loads (lane owns float4 #lane of each row), 4 candidates per iteration.
// (exact round-15 / best configuration)
__global__ void k_rescore(const float* __restrict__ emb, float* __restrict__ dout) {
    int wid = threadIdx.x >> 5, lane = threadIdx.x & 31;
    int row = blockIdx.x * 8 + wid;
    float4 z4 = ((const float4*)(g_z + (size_t)row * CDIM))[lane];
    float zs = g_zsq[row];
    int cnt = g_ccnt[row];

    float best = 3.0e38f; int bidx = 0x7fffffff;
    if (cnt <= CAP) {
        for (int c0 = 0; c0 < cnt; c0 += 4) {
            int nc = cnt - c0; if (nc > 4) nc = 4;
            int idx[4]; float p[4];
            #pragma unroll
            for (int j = 0; j < 4; j++) {
                int c = c0 + ((j < nc) ? j : 0);
                idx[j] = g_cidx[row*CAP + c];
                float4 e4 = ((const float4*)(emb + (size_t)idx[j] * CDIM))[lane];
                p[j] = fmaf(z4.x, e4.x, fmaf(z4.y, e4.y, fmaf(z4.z, e4.z, z4.w*e4.w)));
            }
            #pragma unroll
            for (int o = 16; o > 0; o >>= 1) {
                #pragma unroll
                for (int j = 0; j < 4; j++)
                    p[j] += __shfl_xor_sync(0xffffffffu, p[j], o);
            }
            #pragma unroll
            for (int j = 0; j < 4; j++) {
                if (j < nc) {
                    float d = __fsub_rn(__fadd_rn(zs, g_esq[idx[j]]), __fmul_rn(2.0f, p[j]));
                    if (d < best || (d == best && idx[j] < bidx)) { best = d; bidx = idx[j]; }
                }
            }
        }
    } else {
        // overflow fallback: full scan, 4 codes per iteration
        for (int c0 = 0; c0 < KCODES; c0 += 4) {
            float p[4];
            #pragma unroll
            for (int j = 0; j < 4; j++) {
                float4 e4 = ((const float4*)(emb + (size_t)(c0 + j) * CDIM))[lane];
                p[j] = fmaf(z4.x, e4.x, fmaf(z4.y, e4.y, fmaf(z4.z, e4.z, z4.w*e4.w)));
            }
            #pragma unroll
            for (int o = 16; o > 0; o >>= 1) {
                #pragma unroll
                for (int j = 0; j < 4; j++)
                    p[j] += __shfl_xor_sync(0xffffffffu, p[j], o);
            }
            #pragma unroll
            for (int j = 0; j < 4; j++) {
                float d = __fsub_rn(__fadd_rn(zs, g_esq[c0 + j]), __fmul_rn(2.0f, p[j]));
                if (d < best) { best = d; bidx = c0 + j; }
            }
        }
    }
    if (lane == 0) {
        g_idx[row] = bidx;
        dout[IDX_OFF + row] = (float)bidx;
        atomicAdd(&g_hist[bidx], 1u);
    }
}

// ---------------------------------------------------------------------------
// Gather + BCHW output + SSE partials + (last block) final scalars.
__global__ void k_output(const float* __restrict__ emb, float* __restrict__ dout) {
    __shared__ float se[CDIM*(WW+1)];
    __shared__ float sz[CDIM*(WW+1)];
    __shared__ int   sidx[WW];
    __shared__ float sred[8];
    __shared__ float sr[256];
    __shared__ unsigned s_last;
    int bh = blockIdx.x;
    int b = bh >> 5, h = bh & 31;
    int nbase = bh * WW;
    int tid = threadIdx.x;   // 256

    if (tid < WW) sidx[tid] = g_idx[nbase + tid];
    __syncthreads();

    for (int e = tid; e < WW*CDIM; e += 256) {
        int w = e >> 7, c = e & 127;
        se[c*(WW+1) + w] = emb[(size_t)sidx[w]*CDIM + c];
        sz[c*(WW+1) + w] = g_z[(size_t)(nbase+w)*CDIM + c];
    }
    __syncthreads();

    float lsse = 0.f;
    for (int e = tid; e < CDIM*WW; e += 256) {
        int c = e >> 5, w = e & 31;
        float q  = se[c*(WW+1) + w];
        float zz = sz[c*(WW+1) + w];
        float df = q - zz;
        lsse += df*df;
        dout[OUT_OFF + (((size_t)(b*CDIM + c))*HH + h)*WW + w] = q;
    }
    #pragma unroll
    for (int o = 16; o > 0; o >>= 1) lsse += __shfl_xor_sync(0xffffffffu, lsse, o);
    if ((tid & 31) == 0) sred[tid >> 5] = lsse;
    __syncthreads();
    if (tid == 0) {
        float s = 0.f;
        #pragma unroll
        for (int i = 0; i < 8; i++) s += sred[i];
        g_part[bh] = s;
        __threadfence();
        unsigned prev = atomicAdd(&g_done, 1u);
        s_last = (prev == (unsigned)(BB*HH - 1)) ? 1u : 0u;
    }
    __syncthreads();

    // last block computes loss + perplexity (fp32, same math as before)
    if (s_last) {
        float s = 0.f;
        for (int i = tid; i < 1024; i += 256) s += g_part[i];
        sr[tid] = s; __syncthreads();
        for (int o = 128; o > 0; o >>= 1) {
            if (tid < o) sr[tid] += sr[tid + o];
            __syncthreads();
        }
        if (tid == 0) {
            float mse = sr[0] / (float)(NROWS*CDIM);
            dout[0] = 1.25f * mse;
        }
        __syncthreads();
        float hs = 0.f;
        for (int k = tid; k < KCODES; k += 256) {
            float p = (float)g_hist[k] / (float)NROWS;
            hs += p * logf(p + 1e-10f);
        }
        sr[tid] = hs; __syncthreads();
        for (int o = 128; o > 0; o >>= 1) {
            if (tid < o) sr[tid] += sr[tid + o];
            __syncthreads();
        }
        if (tid == 0) dout[PERP_OFF] = expf(-sr[0]);
    }
}

// ---------------------------------------------------------------------------
extern "C" void kernel_launch(void* const* d_in, const int* in_sizes, int n_in,
                              void* d_out, int out_size) {
    const float* x   = (const float*)d_in[0];
    const float* Wl  = (const float*)d_in[1];
    const float* bl  = (const float*)d_in[2];
    const float* emb = (const float*)d_in[3];
    float* dout = (float*)d_out;

    cudaFuncSetAttribute(k_gemm, cudaFuncAttributeMaxDynamicSharedMemorySize, SMEM_GEMM);

    k_esq<<<(KCODES*32)/256, 256>>>(emb, Wl);
    k_linear<<<BB*HH, 128>>>(x, bl);
    k_gemm<<<NROWS/RM, 1024, SMEM_GEMM>>>();
    k_rescore<<<NROWS/8, 256>>>(emb, dout);
    k_output<<<BB*HH, 256>>>(emb, dout);
}